// round 17
// baseline (speedup 1.0000x reference)
#include <cuda_runtime.h>
#include <cstddef>
#include <cstdint>

// Sizes: B=64, S=1024, E=256 (== proj dim), H=1024, G=4*H=4096
#define NB 64
#define NS 1024
#define NE 256
#define NH 1024
#define NG 4096
#define RBLK 128     // 64 blocks per direction, 1/SM

// phase-2 smem pool (float offsets)
#define WHH_OFF 0                 // 8 chunks x [64][36]          = 18432
#define WHR_OFF 18432             // [16][1028]                   = 16448
#define AB_OFF 34880              // gates ping-pong 2kg x 2 x 2304 = 9216
                                  //   aliased: proj A 16 warps x [16][68] = 17408
#define GS_OFF 52288              // gs 64x65 = 4160 / PART 256x17 = 4352
#define POOL_FLOATS 56640         // 226560 bytes
// phase-1 aliases (phase-separated by grid barrier)
#define P1_WS 0                   // 8*2304 = 18432
#define P1_AB 18432               // 4*2304 = 9216
#define P1_GS 27648               // 64*65  = 4160

// ---------------- device scratch (static: no runtime allocation) ------------
__device__ float g_xg[2][(size_t)NS * NB * NG];  // 2 GiB  xg [dir][s][b][g]
__device__ float g_xq[(size_t)NB * NS * NE];     // 64 MB  x rounded to tf32
__device__ float g_hq[2][2][NB * NE];            // [parity][dir] rounded h
__device__ float g_a[2][NB * NH];                // [dir][b*1024+j] rounded
__device__ unsigned g_ctr[4];
__device__ unsigned g_flagA[2][64 * 16];         // a(t) published (value t+1)
__device__ unsigned g_flagH[2][64 * 16];         // h(t+1) published (value t+1)

__device__ __forceinline__ float sigf(float x) { return 1.0f / (1.0f + __expf(-x)); }
__device__ __forceinline__ float tanh_f(float x) {
    float e = __expf(2.0f * x);
    return 1.0f - 2.0f / (e + 1.0f);
}

__device__ __forceinline__ uint4 cvt4(float4 v) {
    uint4 u;
    asm("cvt.rna.tf32.f32 %0, %1;" : "=r"(u.x) : "f"(v.x));
    asm("cvt.rna.tf32.f32 %0, %1;" : "=r"(u.y) : "f"(v.y));
    asm("cvt.rna.tf32.f32 %0, %1;" : "=r"(u.z) : "f"(v.z));
    asm("cvt.rna.tf32.f32 %0, %1;" : "=r"(u.w) : "f"(v.w));
    return u;
}
__device__ __forceinline__ float cvt1(float v) {
    uint32_t u;
    asm("cvt.rna.tf32.f32 %0, %1;" : "=r"(u) : "f"(v));
    return __uint_as_float(u);
}

__device__ __forceinline__ void mma_tf32(float* acc,
                                         uint32_t a0, uint32_t a1, uint32_t a2, uint32_t a3,
                                         uint32_t b0, uint32_t b1) {
    asm volatile(
        "mma.sync.aligned.m16n8k8.row.col.f32.tf32.tf32.f32 "
        "{%0,%1,%2,%3}, {%4,%5,%6,%7}, {%8,%9}, {%0,%1,%2,%3};"
        : "+f"(acc[0]), "+f"(acc[1]), "+f"(acc[2]), "+f"(acc[3])
        : "r"(a0), "r"(a1), "r"(a2), "r"(a3), "r"(b0), "r"(b1));
}

// one 32-wide K chunk of warp MMA; A/B in smem row-major stride 36
template <int NTS>
__device__ __forceinline__ void warp_mma_chunk(const uint32_t* __restrict__ Au,
                                               const uint32_t* __restrict__ Bu,
                                               int mg, int ngb, int l,
                                               float acc[][4]) {
#pragma unroll
    for (int ks = 0; ks < 4; ks++) {
        int k0 = ks * 8 + (l & 3);
        int ra = (mg + (l >> 2)) * 36 + k0;
        uint32_t a0 = Au[ra];
        uint32_t a1 = Au[ra + 8 * 36];
        uint32_t a2 = Au[ra + 4];
        uint32_t a3 = Au[ra + 8 * 36 + 4];
#pragma unroll
        for (int nt = 0; nt < NTS; nt++) {
            int rb = (ngb + nt * 8 + (l >> 2)) * 36 + k0;
            mma_tf32(acc[nt], a0, a1, a2, a3, Bu[rb], Bu[rb + 4]);
        }
    }
}

// 256-thread (kg-group) A-chunk fill: 64 rows x 32 cols
__device__ __forceinline__ void fillA_raw(float* __restrict__ dst,
                                          const float* __restrict__ src,
                                          int k0, size_t rowstride, int t2) {
#pragma unroll
    for (int i = 0; i < 2; i++) {
        int f = t2 + i * 256;
        int r = f >> 3;
        int kq = (f & 7) << 2;
        float4 v = __ldcg((const float4*)&src[(size_t)r * rowstride + k0 + kq]);
        *(float4*)&dst[r * 36 + kq] = v;
    }
}

__device__ __forceinline__ unsigned ldacq(const unsigned* p) {
    unsigned v;
    asm volatile("ld.global.acquire.gpu.u32 %0, [%1];" : "=r"(v) : "l"(p) : "memory");
    return v;
}
__device__ __forceinline__ void strel(unsigned* p, unsigned v) {
    asm volatile("st.global.release.gpu.u32 [%0], %1;" :: "l"(p), "r"(v) : "memory");
}

__device__ __forceinline__ void gbar(unsigned* c, unsigned target) {
    __syncthreads();
    if (threadIdx.x == 0) {
        __threadfence();
        atomicAdd(c, 1u);
        unsigned v;
        do { v = ldacq(c); } while (v < target);
    }
    __syncthreads();
}

#define BARKG() asm volatile("bar.sync %0, %1;" :: "r"(kg + 1), "r"(256) : "memory")

// --------------------------- init ------------------------------------------
__global__ void init_kernel() {
    int i = blockIdx.x * blockDim.x + threadIdx.x;   // 128 x 512 = 65536
    if (i < 4) g_ctr[i] = 0u;
    if (i < 2 * 64 * 16) {
        (&g_flagA[0][0])[i] = 0u;
        (&g_flagH[0][0])[i] = 0u;
    }
    if (i < 2 * 2 * NB * NE) (&g_hq[0][0][0])[i] = 0.0f;
}

// --------------------------- the whole network ------------------------------
__global__ __launch_bounds__(512, 1) void lstm_kernel(
    const float* __restrict__ x,
    const float* __restrict__ Wihf, const float* __restrict__ Whhf,
    const float* __restrict__ bihf, const float* __restrict__ bhhf,
    const float* __restrict__ Whrf,
    const float* __restrict__ Wihb, const float* __restrict__ Whhb,
    const float* __restrict__ bihb, const float* __restrict__ bhhb,
    const float* __restrict__ Whrb,
    float* __restrict__ out)
{
    extern __shared__ __align__(16) float pool[];

    const int bid = blockIdx.x;
    const int tid = threadIdx.x;
    const int l   = tid & 31;
    const int wid = tid >> 5;          // warp 0..15
    const int dir = bid >> 6;
    const int u   = bid & 63;
    const int kg  = tid >> 8;          // K group 0/1
    const int t2  = tid & 255;
    const int wi  = t2 >> 5;           // warp-in-group 0..7
    const int mg1 = (wi & 3) << 4;
    const int ngb = (wi >> 2) << 5;

    // ---------------- phase 0: round x into g_xq ----------------------------
    {
        const size_t n4 = (size_t)NB * NS * NE / 4;
        for (size_t i4 = (size_t)bid * 512 + tid; i4 < n4; i4 += (size_t)RBLK * 512) {
            float4 v = ((const float4*)x)[i4];
            *(uint4*)&((float4*)g_xq)[i4] = cvt4(v);
        }
    }
    gbar(&g_ctr[0], (unsigned)RBLK);

    // ---------------- phase 1: xg = x @ W_ih^T + (b_ih + b_hh)  (R11) -------
    {
        const int n0 = u << 6;
        const float* __restrict__ W  = dir ? Wihb : Wihf;
        const float* __restrict__ bi = dir ? bihb : bihf;
        const float* __restrict__ bh = dir ? bhhb : bhhf;
        float* __restrict__ xo = g_xg[dir];
        uint32_t* WS = (uint32_t*)(pool + P1_WS);
        float* Ab = pool + P1_AB + kg * 2 * 2304;
        float* gs1 = pool + P1_GS;

#pragma unroll
        for (int ci = 0; ci < 8; ci++) {
            int r = tid >> 3;
            int kq = (tid & 7) << 2;
            float4 wv = *(const float4*)&W[(size_t)(n0 + r) * NE + ci * 32 + kq];
            *(uint4*)&WS[ci * 2304 + r * 36 + kq] = cvt4(wv);
        }
        float bias0[4], bias1[4];
#pragma unroll
        for (int nt = 0; nt < 4; nt++) {
            int c = ngb + nt * 8 + ((l & 3) << 1);
            bias0[nt] = bi[n0 + c] + bh[n0 + c];
            bias1[nt] = bi[n0 + c + 1] + bh[n0 + c + 1];
        }
        __syncthreads();

        for (int s = 0; s < NS; s++) {
            const float* xsrc = g_xq + (size_t)s * NE;
            float acc[4][4];
#pragma unroll
            for (int a = 0; a < 4; a++)
#pragma unroll
                for (int q = 0; q < 4; q++) acc[a][q] = 0.0f;

            fillA_raw(Ab, xsrc, kg * 128, (size_t)NS * NE, t2);
            __syncthreads();
#pragma unroll
            for (int rr = 0; rr < 4; rr++) {
                if (rr < 3)
                    fillA_raw(Ab + ((rr + 1) & 1) * 2304, xsrc,
                              kg * 128 + (rr + 1) * 32, (size_t)NS * NE, t2);
                warp_mma_chunk<4>((uint32_t*)(Ab + (rr & 1) * 2304),
                                  WS + (kg * 4 + rr) * 2304, mg1, ngb, l, acc);
                __syncthreads();
            }
            if (kg == 1) {
#pragma unroll
                for (int nt = 0; nt < 4; nt++) {
                    int c = ngb + nt * 8 + ((l & 3) << 1);
                    int r = mg1 + (l >> 2);
                    gs1[c * 65 + r]           = acc[nt][0];
                    gs1[(c + 1) * 65 + r]     = acc[nt][1];
                    gs1[c * 65 + r + 8]       = acc[nt][2];
                    gs1[(c + 1) * 65 + r + 8] = acc[nt][3];
                }
            }
            __syncthreads();
            if (kg == 0) {
#pragma unroll
                for (int nt = 0; nt < 4; nt++) {
                    int c = ngb + nt * 8 + ((l & 3) << 1);
                    int r = mg1 + (l >> 2);
                    float2 o0, o1;
                    o0.x = acc[nt][0] + gs1[c * 65 + r] + bias0[nt];
                    o0.y = acc[nt][1] + gs1[(c + 1) * 65 + r] + bias1[nt];
                    o1.x = acc[nt][2] + gs1[c * 65 + r + 8] + bias0[nt];
                    o1.y = acc[nt][3] + gs1[(c + 1) * 65 + r + 8] + bias1[nt];
                    __stcs((float2*)&xo[((size_t)s * NB + r) * NG + n0 + c], o0);
                    __stcs((float2*)&xo[((size_t)s * NB + r + 8) * NG + n0 + c], o1);
                }
            }
            __syncthreads();
        }
    }
    gbar(&g_ctr[0], 2u * RBLK);

    // ---------------- phase 2: the recurrence (dataflow waits) --------------
    const float* __restrict__ Whh = dir ? Whhb : Whhf;
    const float* __restrict__ Whr = dir ? Whrb : Whrf;
    const float* __restrict__ xg  = g_xg[dir];
    unsigned* flgA = &g_flagA[dir][0];
    unsigned* flgH = &g_flagH[dir][0];

    const int j0 = u << 4;                     // gates: 16 hidden units
    const int b0 = (u >> 4) << 4;              // proj: 16-batch tile
    const int p0 = (u & 15) << 4;              // proj: 16-col tile

    uint32_t* WhhS = (uint32_t*)(pool + WHH_OFF);
    uint32_t* WhrS = (uint32_t*)(pool + WHR_OFF);
    float* Ab2 = pool + AB_OFF + kg * 4608;    // gates ping-pong (per kg)
    float* APw = pool + AB_OFF + wid * 1088;   // proj per-warp [16][68] (alias)
    float* gs  = pool + GS_OFF;                // gates out / proj partials

    // ---- weights into smem ONCE (pre-converted tf32) -----------------------
#pragma unroll
    for (int ci = 0; ci < 8; ci++) {           // Whh chunk ci = cols [32ci,32ci+32)
        int r = tid >> 3;
        int kq = (tid & 7) << 2;
        int g = ((r >> 4) << 10) + j0 + (r & 15);
        float4 wv = *(const float4*)&Whh[(size_t)g * NE + ci * 32 + kq];
        *(uint4*)&WhhS[ci * 2304 + r * 36 + kq] = cvt4(wv);
    }
#pragma unroll
    for (int i = 0; i < 8; i++) {
        int f = tid + i * 512;
        int c = f >> 8;
        int kq = (f & 255) << 2;
        float4 wv = *(const float4*)&Whr[(size_t)(p0 + c) * NH + kq];
        *(uint4*)&WhrS[c * 1028 + kq] = cvt4(wv);
    }
    __syncthreads();

    float creg[2] = {0.0f, 0.0f};

    for (int t = 0; t < NS; t++) {
        const int par = t & 1;
        const float* __restrict__ h = g_hq[par][dir];
        const int s_eff = dir ? (NS - 1 - t) : t;

        // xg prefetch (DRAM latency overlapped with first-chunk wait)
        float xgi[2], xgf[2], xgg[2], xgo[2];
#pragma unroll
        for (int i = 0; i < 2; i++) {
            int m = tid + i * 512;
            int jj = m & 15, b = m >> 4;
            const float* p = &xg[((size_t)s_eff * NB + b) * NG + j0 + jj];
            xgi[i] = __ldcs(p);
            xgf[i] = __ldcs(p + 1024);
            xgg[i] = __ldcs(p + 2048);
            xgo[i] = __ldcs(p + 3072);
        }

        // ---- gates: chunk-dataflow over 8 producers per 32-col chunk ------
        {
            float acc[4][4];
#pragma unroll
            for (int a = 0; a < 4; a++)
#pragma unroll
                for (int q = 0; q < 4; q++) acc[a][q] = 0.0f;

            // chunk k0(rr) = rr*64 + kg*32; producers: u = b*16 + (k0>>4)+{0,1}
            // poll helper inline (first warp of the kg group, lanes 0..7)
            // chunk 0
            if (t > 0 && t2 < 32 && l < 8) {
                int pi = ((kg * 32) >> 4) + (l & 1);
                int up = ((l >> 1) << 4) + pi;
                while (ldacq(&flgH[up * 16]) < (unsigned)t) { }
            }
            BARKG();
            fillA_raw(Ab2, h, kg * 32, NE, t2);
            // chunk 1
            if (t > 0 && t2 < 32 && l < 8) {
                int pi = ((64 + kg * 32) >> 4) + (l & 1);
                int up = ((l >> 1) << 4) + pi;
                while (ldacq(&flgH[up * 16]) < (unsigned)t) { }
            }
            BARKG();
#pragma unroll
            for (int rr = 0; rr < 4; rr++) {
                if (rr < 3)
                    fillA_raw(Ab2 + ((rr + 1) & 1) * 2304, h,
                              (rr + 1) * 64 + kg * 32, NE, t2);
                warp_mma_chunk<4>((uint32_t*)(Ab2 + (rr & 1) * 2304),
                                  WhhS + (rr * 2 + kg) * 2304, mg1, ngb, l, acc);
                if (rr < 2 && t > 0 && t2 < 32 && l < 8) {
                    int pi = (((rr + 2) * 64 + kg * 32) >> 4) + (l & 1);
                    int up = ((l >> 1) << 4) + pi;
                    while (ldacq(&flgH[up * 16]) < (unsigned)t) { }
                }
                BARKG();
            }
            // kg merge into gs (block-wide)
            if (kg == 1) {
#pragma unroll
                for (int nt = 0; nt < 4; nt++) {
                    int c = ngb + nt * 8 + ((l & 3) << 1);
                    int r = mg1 + (l >> 2);
                    gs[c * 65 + r]           = acc[nt][0];
                    gs[(c + 1) * 65 + r]     = acc[nt][1];
                    gs[c * 65 + r + 8]       = acc[nt][2];
                    gs[(c + 1) * 65 + r + 8] = acc[nt][3];
                }
            }
            __syncthreads();
            if (kg == 0) {
#pragma unroll
                for (int nt = 0; nt < 4; nt++) {
                    int c = ngb + nt * 8 + ((l & 3) << 1);
                    int r = mg1 + (l >> 2);
                    gs[c * 65 + r]           += acc[nt][0];
                    gs[(c + 1) * 65 + r]     += acc[nt][1];
                    gs[c * 65 + r + 8]       += acc[nt][2];
                    gs[(c + 1) * 65 + r + 8] += acc[nt][3];
                }
            }
            __syncthreads();
        }

        // ---- cell update (c in registers), rounded a to global ------------
#pragma unroll
        for (int i = 0; i < 2; i++) {
            int m = tid + i * 512;
            int jj = m & 15, b = m >> 4;
            float gi = gs[( 0 + jj) * 65 + b] + xgi[i];
            float gf = gs[(16 + jj) * 65 + b] + xgf[i];
            float gg = gs[(32 + jj) * 65 + b] + xgg[i];
            float go = gs[(48 + jj) * 65 + b] + xgo[i];
            float cn = sigf(gf) * creg[i] + sigf(gi) * tanh_f(gg);
            creg[i] = cn;
            g_a[dir][b * NH + j0 + jj] = cvt1(sigf(go) * tanh_f(cn));
        }
        __syncthreads();
        if (tid == 0) {
            __threadfence();
            strel(&flgA[u * 16], (unsigned)(t + 1));
        }

        // ---- projection (per-warp dataflow): warp w waits 4 producers -----
        float outv = 0.0f; int outb = 0, outp = 0;
        {
            if (l < 4) {
                while (ldacq(&flgA[(wid * 4 + l) * 16]) < (unsigned)(t + 1)) { }
            }
            __syncwarp();

            // fill own K-slice: rows b0..b0+15, cols [64w, 64w+64)
#pragma unroll
            for (int i = 0; i < 8; i++) {
                int idx = i * 32 + l;
                int r = idx >> 4;
                int c4 = (idx & 15) << 2;
                float4 v = __ldcg((const float4*)
                    &g_a[dir][(size_t)(b0 + r) * NH + wid * 64 + c4]);
                *(float4*)&APw[r * 68 + c4] = v;
            }
            __syncwarp();

            const uint32_t* aU = (const uint32_t*)APw;
            float pacc[2][4];
#pragma unroll
            for (int nt = 0; nt < 2; nt++)
#pragma unroll
                for (int q = 0; q < 4; q++) pacc[nt][q] = 0.0f;

#pragma unroll
            for (int ks = 0; ks < 8; ks++) {
                int kb = ks * 8 + (l & 3);
                int ra = (l >> 2) * 68 + kb;
                uint32_t a0 = aU[ra];
                uint32_t a1 = aU[ra + 8 * 68];
                uint32_t a2 = aU[ra + 4];
                uint32_t a3 = aU[ra + 8 * 68 + 4];
                int kglob = wid * 64 + kb;
#pragma unroll
                for (int nt = 0; nt < 2; nt++) {
                    int rb = (nt * 8 + (l >> 2)) * 1028 + kglob;
                    mma_tf32(pacc[nt], a0, a1, a2, a3, WhrS[rb], WhrS[rb + 4]);
                }
            }
            // partials -> gs[(r*16+c)*17 + wid]  (gs free after cell)
#pragma unroll
            for (int nt = 0; nt < 2; nt++) {
                int c0 = nt * 8 + ((l & 3) << 1);
                int r0 = l >> 2;
                gs[(r0 * 16 + c0) * 17 + wid]           = pacc[nt][0];
                gs[(r0 * 16 + c0 + 1) * 17 + wid]       = pacc[nt][1];
                gs[((r0 + 8) * 16 + c0) * 17 + wid]     = pacc[nt][2];
                gs[((r0 + 8) * 16 + c0 + 1) * 17 + wid] = pacc[nt][3];
            }
            __syncthreads();

            // reduce 16 partials; write ONLY g_hq before the fence
            if (tid < 256) {
                float v = 0.0f;
#pragma unroll
                for (int w = 0; w < 16; w++) v += gs[tid * 17 + w];
                outb = b0 + (tid >> 4);
                outp = p0 + (tid & 15);
                outv = v;
                g_hq[par ^ 1][dir][outb * NE + outp] = cvt1(v);
            }
            __syncthreads();
            if (tid == 0) {
                __threadfence();
                strel(&flgH[u * 16], (unsigned)(t + 1));
            }
            // out[] DRAM writes AFTER the publish — off the fence path
            if (tid < 256) {
                out[((size_t)outb * NS + s_eff) * (2 * NE) + dir * NE + outp] = outv;
            }
        }
    }
}

// ----------------------------- launcher -------------------------------------
extern "C" void kernel_launch(void* const* d_in, const int* in_sizes, int n_in,
                              void* d_out, int out_size) {
    (void)in_sizes; (void)n_in; (void)out_size;
    const float* x    = (const float*)d_in[0];
    const float* Wihf = (const float*)d_in[1];
    const float* Whhf = (const float*)d_in[2];
    const float* bihf = (const float*)d_in[3];
    const float* bhhf = (const float*)d_in[4];
    const float* Whrf = (const float*)d_in[5];
    const float* Wihb = (const float*)d_in[6];
    const float* Whhb = (const float*)d_in[7];
    const float* bihb = (const float*)d_in[8];
    const float* bhhb = (const float*)d_in[9];
    const float* Whrb = (const float*)d_in[10];
    float* out = (float*)d_out;

    cudaFuncSetAttribute(lstm_kernel,
                         cudaFuncAttributeMaxDynamicSharedMemorySize,
                         POOL_FLOATS * 4);
    init_kernel<<<128, 512>>>();
    lstm_kernel<<<RBLK, 512, POOL_FLOATS * 4>>>(
        x, Wihf, Whhf, bihf, bhhf, Whrf,
        Wihb, Whhb, bihb, bhhb, Whrb, out);
}